// round 11
// baseline (speedup 1.0000x reference)
#include <cuda_runtime.h>
#include <cuda_fp16.h>
#include <math.h>

#define N_NODES 50000
#define N_EDGES 800000
#define HEADS   4
#define F       32
#define DIM     128
#define DIM2    256   // interleaved row: [A 128 | P 128]

typedef unsigned long long ull;

// ---------------- device scratch ----------------
__device__ __half g_ft16[N_NODES * DIM2];    // interleaved fp16 ft, both streams
__device__ float  g_h_a [N_NODES * DIM];     // layer-0 output (fp32, GEMM input)
__device__ float  g_h_p [N_NODES * DIM];
__device__ float  g_el2 [N_NODES * 8];       // [node][A 4 heads | P 4 heads]
__device__ float  g_er2 [N_NODES * 8];
__device__ int    g_rowptr[N_NODES + 1];
__device__ int    g_cnt [N_NODES];           // zero-init; every call leaves it zeroed
__device__ int    g_src_csr[N_EDGES];
__device__ float2 g_ew_csr[N_EDGES];         // {am_exist, exist}

// ---------------- f32x2 helpers ----------------
__device__ __forceinline__ ull dup2(float v) {
    ull r; asm("mov.b64 %0, {%1, %1};" : "=l"(r) : "f"(v)); return r;
}
__device__ __forceinline__ ull pk2(float a, float b) {
    ull r; asm("mov.b64 %0, {%1, %2};" : "=l"(r) : "f"(a), "f"(b)); return r;
}
__device__ __forceinline__ void ffma2(ull& d, ull a, ull b) {
    asm("fma.rn.f32x2 %0, %1, %2, %3;" : "=l"(d) : "l"(a), "l"(b), "l"(d));
}
__device__ __forceinline__ void unpk2(ull v, float& lo, float& hi) {
    asm("mov.b64 {%0, %1}, %2;" : "=f"(lo), "=f"(hi) : "l"(v));
}

// ---------------- CSR build (3 kernels; cnt self-restoring to 0) ----------------
__global__ void hist_kernel(const int* __restrict__ dst) {
    int i = blockIdx.x * blockDim.x + threadIdx.x;
    if (i < N_EDGES) atomicAdd(&g_cnt[dst[i]], 1);
}

__global__ void scan_kernel() {
    __shared__ int tmp[1024];
    int tid = threadIdx.x;
    const int chunk = (N_NODES + 1023) / 1024;
    int begin = tid * chunk;
    int end   = begin + chunk; if (end > N_NODES) end = N_NODES;
    int sum = 0;
    for (int i = begin; i < end && begin < N_NODES; i++) sum += g_cnt[i];
    tmp[tid] = sum;
    __syncthreads();
    for (int off = 1; off < 1024; off <<= 1) {
        int v = (tid >= off) ? tmp[tid - off] : 0;
        __syncthreads();
        tmp[tid] += v;
        __syncthreads();
    }
    int run = tmp[tid] - sum;
    for (int i = begin; i < end && begin < N_NODES; i++) {
        g_rowptr[i] = run;
        run += g_cnt[i];
    }
    if (tid == 1023) g_rowptr[N_NODES] = tmp[1023];
}

// scatter decrements cnt -> leaves cnt[d] == 0 afterwards
__global__ void scatter_kernel(const int* __restrict__ src, const int* __restrict__ dst,
                               const float* __restrict__ ewa, const float* __restrict__ ewp) {
    int i = blockIdx.x * blockDim.x + threadIdx.x;
    if (i < N_EDGES) {
        int d = dst[i];
        int old = atomicAdd(&g_cnt[d], -1);          // old in [1..deg]
        int pos = g_rowptr[d] + old - 1;
        g_src_csr[pos] = src[i];
        g_ew_csr[pos]  = make_float2(ewa[i], ewp[i]);
    }
}

// ---------------- GEMM (f32x2, 8x8 thread tile) + fused el/er; fp16 interleaved ft out ----
// Block tile 128x128, 256 threads: tx (0..15) -> 8 cols, ty (0..15) -> 8 contiguous rows.
__global__ __launch_bounds__(256) void gemm_kernel(
    const float* __restrict__ A0, const float* __restrict__ A1,
    const float* __restrict__ W0, const float* __restrict__ W1,
    const float* __restrict__ al0, const float* __restrict__ al1,
    const float* __restrict__ ar0, const float* __restrict__ ar1,
    __half* __restrict__ C)
{
    int st = blockIdx.y;
    const float* A  = st ? A1  : A0;
    const float* W  = st ? W1  : W0;
    const float* al = st ? al1 : al0;
    const float* ar = st ? ar1 : ar0;

    __shared__ __align__(16) float Ws[32 * 128];     // 16 KB [kk][n]
    __shared__ __align__(16) ull   Xp[32 * 128];     // 32 KB [kk][row] duplicated {a,a}

    int tid = threadIdx.x;
    int m0  = blockIdx.x * 128;
    int tx  = tid & 15;          // 8 cols: tx*8 .. tx*8+7
    int ty  = tid >> 4;          // 8 rows: ty*8 .. ty*8+7

    ull acc[8][4];
#pragma unroll
    for (int i = 0; i < 8; i++)
#pragma unroll
        for (int j = 0; j < 4; j++) acc[i][j] = 0ull;

    for (int kb = 0; kb < 128; kb += 32) {
        for (int i = tid * 4; i < 32 * 128; i += 1024)
            *reinterpret_cast<float4*>(&Ws[i]) =
                *reinterpret_cast<const float4*>(&W[(kb + (i >> 7)) * 128 + (i & 127)]);
        for (int i = tid; i < 128 * 8; i += 256) {
            int r = i & 127, kk4 = i >> 7;
            int m = m0 + r;
            float4 x4 = (m < N_NODES)
                ? *reinterpret_cast<const float4*>(&A[(size_t)m * 128 + kb + kk4 * 4])
                : make_float4(0.f, 0.f, 0.f, 0.f);
            Xp[(kk4 * 4 + 0) * 128 + r] = dup2(x4.x);
            Xp[(kk4 * 4 + 1) * 128 + r] = dup2(x4.y);
            Xp[(kk4 * 4 + 2) * 128 + r] = dup2(x4.z);
            Xp[(kk4 * 4 + 3) * 128 + r] = dup2(x4.w);
        }
        __syncthreads();
#pragma unroll 4
        for (int kk = 0; kk < 32; kk++) {
            float4 b0 = *reinterpret_cast<const float4*>(&Ws[kk * 128 + tx * 8]);
            float4 b1 = *reinterpret_cast<const float4*>(&Ws[kk * 128 + tx * 8 + 4]);
            ull bb0 = pk2(b0.x, b0.y);
            ull bb1 = pk2(b0.z, b0.w);
            ull bb2 = pk2(b1.x, b1.y);
            ull bb3 = pk2(b1.z, b1.w);
            const ulonglong2* xr = reinterpret_cast<const ulonglong2*>(&Xp[kk * 128 + ty * 8]);
            ulonglong2 x01 = xr[0], x23 = xr[1], x45 = xr[2], x67 = xr[3];
            ull xs0 = x01.x, xs1 = x01.y, xs2 = x23.x, xs3 = x23.y;
            ull xs4 = x45.x, xs5 = x45.y, xs6 = x67.x, xs7 = x67.y;
            ffma2(acc[0][0], xs0, bb0); ffma2(acc[0][1], xs0, bb1);
            ffma2(acc[0][2], xs0, bb2); ffma2(acc[0][3], xs0, bb3);
            ffma2(acc[1][0], xs1, bb0); ffma2(acc[1][1], xs1, bb1);
            ffma2(acc[1][2], xs1, bb2); ffma2(acc[1][3], xs1, bb3);
            ffma2(acc[2][0], xs2, bb0); ffma2(acc[2][1], xs2, bb1);
            ffma2(acc[2][2], xs2, bb2); ffma2(acc[2][3], xs2, bb3);
            ffma2(acc[3][0], xs3, bb0); ffma2(acc[3][1], xs3, bb1);
            ffma2(acc[3][2], xs3, bb2); ffma2(acc[3][3], xs3, bb3);
            ffma2(acc[4][0], xs4, bb0); ffma2(acc[4][1], xs4, bb1);
            ffma2(acc[4][2], xs4, bb2); ffma2(acc[4][3], xs4, bb3);
            ffma2(acc[5][0], xs5, bb0); ffma2(acc[5][1], xs5, bb1);
            ffma2(acc[5][2], xs5, bb2); ffma2(acc[5][3], xs5, bb3);
            ffma2(acc[6][0], xs6, bb0); ffma2(acc[6][1], xs6, bb1);
            ffma2(acc[6][2], xs6, bb2); ffma2(acc[6][3], xs6, bb3);
            ffma2(acc[7][0], xs7, bb0); ffma2(acc[7][1], xs7, bb1);
            ffma2(acc[7][2], xs7, bb2); ffma2(acc[7][3], xs7, bb3);
        }
        __syncthreads();
    }

    // epilogue: fp16 store + fused el/er (cols tx*8..tx*8+7 all within head tx>>2)
    float4 alv0 = *reinterpret_cast<const float4*>(&al[tx * 8]);
    float4 alv1 = *reinterpret_cast<const float4*>(&al[tx * 8 + 4]);
    float4 arv0 = *reinterpret_cast<const float4*>(&ar[tx * 8]);
    float4 arv1 = *reinterpret_cast<const float4*>(&ar[tx * 8 + 4]);
    int head = tx >> 2;

#pragma unroll
    for (int p = 0; p < 8; p++) {
        float f0, f1, f2, f3, f4, f5, f6, f7;
        unpk2(acc[p][0], f0, f1);
        unpk2(acc[p][1], f2, f3);
        unpk2(acc[p][2], f4, f5);
        unpk2(acc[p][3], f6, f7);
        int m = m0 + ty * 8 + p;
        if (m < N_NODES) {
            __half2 h0 = __floats2half2_rn(f0, f1);
            __half2 h1 = __floats2half2_rn(f2, f3);
            __half2 h2 = __floats2half2_rn(f4, f5);
            __half2 h3 = __floats2half2_rn(f6, f7);
            uint4 u;
            u.x = *reinterpret_cast<unsigned*>(&h0);
            u.y = *reinterpret_cast<unsigned*>(&h1);
            u.z = *reinterpret_cast<unsigned*>(&h2);
            u.w = *reinterpret_cast<unsigned*>(&h3);
            *reinterpret_cast<uint4*>(&C[(size_t)m * DIM2 + st * DIM + tx * 8]) = u;
        }
        float l = f0 * alv0.x + f1 * alv0.y + f2 * alv0.z + f3 * alv0.w
                + f4 * alv1.x + f5 * alv1.y + f6 * alv1.z + f7 * alv1.w;
        float r = f0 * arv0.x + f1 * arv0.y + f2 * arv0.z + f3 * arv0.w
                + f4 * arv1.x + f5 * arv1.y + f6 * arv1.z + f7 * arv1.w;
        l += __shfl_xor_sync(0xffffffffu, l, 1);
        r += __shfl_xor_sync(0xffffffffu, r, 1);
        l += __shfl_xor_sync(0xffffffffu, l, 2);
        r += __shfl_xor_sync(0xffffffffu, r, 2);
        if ((tx & 3) == 0 && m < N_NODES) {
            g_el2[m * 8 + st * 4 + head] = l;
            g_er2[m * 8 + st * 4 + head] = r;
        }
    }
}

__device__ __forceinline__ float lrelu(float x) { return x > 0.f ? x : 0.2f * x; }

__device__ __forceinline__ void acc8(float* acc, uint4 u, float p) {
    float2 f0 = __half22float2(*reinterpret_cast<__half2*>(&u.x));
    float2 f1 = __half22float2(*reinterpret_cast<__half2*>(&u.y));
    float2 f2 = __half22float2(*reinterpret_cast<__half2*>(&u.z));
    float2 f3 = __half22float2(*reinterpret_cast<__half2*>(&u.w));
    acc[0] = fmaf(p, f0.x, acc[0]); acc[1] = fmaf(p, f0.y, acc[1]);
    acc[2] = fmaf(p, f1.x, acc[2]); acc[3] = fmaf(p, f1.y, acc[3]);
    acc[4] = fmaf(p, f2.x, acc[4]); acc[5] = fmaf(p, f2.y, acc[5]);
    acc[6] = fmaf(p, f3.x, acc[6]); acc[7] = fmaf(p, f3.y, acc[7]);
}

// ---------------- fused score + aggregation (unchanged from best) ----------------
__global__ __launch_bounds__(256) void agg_kernel(
    const __half* __restrict__ ft,
    const float* __restrict__ biasA, const float* __restrict__ biasP,
    float* __restrict__ outA, float* __restrict__ outP, int mode)
{
    __shared__ float sh_p[8][256];
    int wib  = threadIdx.x >> 5;
    int w    = (blockIdx.x * blockDim.x + threadIdx.x) >> 5;
    int lane = threadIdx.x & 31;
    if (w >= N_NODES) return;
    int node = w;
    int beg = g_rowptr[node], end = g_rowptr[node + 1];
    int part = lane >> 4;
    int q    = lane & 15;
    int h    = q >> 2;
    int r    = q & 3;
    int ph   = part * 4 + h;
    int off  = part * DIM + q * 8;
    float* pw = sh_p[wib];

    float4 erA = *reinterpret_cast<const float4*>(&g_er2[node * 8]);
    float4 erP = *reinterpret_cast<const float4*>(&g_er2[node * 8 + 4]);

    float s[8];
#pragma unroll
    for (int k = 0; k < 8; k++) s[k] = 0.f;
    float acc[8];
#pragma unroll
    for (int k = 0; k < 8; k++) acc[k] = 0.f;

    for (int i0 = beg; i0 < end; i0 += 32) {
        int n = end - i0; if (n > 32) n = 32;
        int sn_l = 0;
        float4 pa = make_float4(0.f, 0.f, 0.f, 0.f);
        float4 pp = make_float4(0.f, 0.f, 0.f, 0.f);
        if (lane < n) {
            int i = i0 + lane;
            sn_l = g_src_csr[i];
            float2 ew  = g_ew_csr[i];
            float4 elA = *reinterpret_cast<const float4*>(&g_el2[sn_l * 8]);
            float4 elP = *reinterpret_cast<const float4*>(&g_el2[sn_l * 8 + 4]);
            float e0 = __expf(fminf(lrelu(elA.x + erA.x), 60.f));
            float e1 = __expf(fminf(lrelu(elA.y + erA.y), 60.f));
            float e2 = __expf(fminf(lrelu(elA.z + erA.z), 60.f));
            float e3 = __expf(fminf(lrelu(elA.w + erA.w), 60.f));
            float e4 = __expf(fminf(lrelu(elP.x + erP.x), 60.f));
            float e5 = __expf(fminf(lrelu(elP.y + erP.y), 60.f));
            float e6 = __expf(fminf(lrelu(elP.z + erP.z), 60.f));
            float e7 = __expf(fminf(lrelu(elP.w + erP.w), 60.f));
            s[0] += e0; s[1] += e1; s[2] += e2; s[3] += e3;
            s[4] += e4; s[5] += e5; s[6] += e6; s[7] += e7;
            pa = make_float4(e0 * ew.x, e1 * ew.x, e2 * ew.x, e3 * ew.x);
            pp = make_float4(e4 * ew.y, e5 * ew.y, e6 * ew.y, e7 * ew.y);
        }
        __syncwarp();
        *reinterpret_cast<float4*>(&pw[lane * 8])     = pa;
        *reinterpret_cast<float4*>(&pw[lane * 8 + 4]) = pp;
        __syncwarp();

        int j = 0;
        for (; j + 4 <= n; j += 4) {
            int t0 = __shfl_sync(0xffffffffu, sn_l, j);
            int t1 = __shfl_sync(0xffffffffu, sn_l, j + 1);
            int t2 = __shfl_sync(0xffffffffu, sn_l, j + 2);
            int t3 = __shfl_sync(0xffffffffu, sn_l, j + 3);
            uint4 u0 = *reinterpret_cast<const uint4*>(&ft[(size_t)t0 * DIM2 + off]);
            uint4 u1 = *reinterpret_cast<const uint4*>(&ft[(size_t)t1 * DIM2 + off]);
            uint4 u2 = *reinterpret_cast<const uint4*>(&ft[(size_t)t2 * DIM2 + off]);
            uint4 u3 = *reinterpret_cast<const uint4*>(&ft[(size_t)t3 * DIM2 + off]);
            acc8(acc, u0, pw[(j    ) * 8 + ph]);
            acc8(acc, u1, pw[(j + 1) * 8 + ph]);
            acc8(acc, u2, pw[(j + 2) * 8 + ph]);
            acc8(acc, u3, pw[(j + 3) * 8 + ph]);
        }
        for (; j < n; j++) {
            int t0 = __shfl_sync(0xffffffffu, sn_l, j);
            uint4 u0 = *reinterpret_cast<const uint4*>(&ft[(size_t)t0 * DIM2 + off]);
            acc8(acc, u0, pw[j * 8 + ph]);
        }
    }

#pragma unroll
    for (int o = 16; o; o >>= 1)
#pragma unroll
        for (int k = 0; k < 8; k++)
            s[k] += __shfl_xor_sync(0xffffffffu, s[k], o);

    float is = 1.f / fmaxf(s[ph], 1e-9f);

    const float* bias = part ? biasP : biasA;
    float4 b0 = *reinterpret_cast<const float4*>(&bias[h * F + r * 8]);
    float4 b1 = *reinterpret_cast<const float4*>(&bias[h * F + r * 8 + 4]);
    acc[0] = fmaf(acc[0], is, b0.x); acc[1] = fmaf(acc[1], is, b0.y);
    acc[2] = fmaf(acc[2], is, b0.z); acc[3] = fmaf(acc[3], is, b0.w);
    acc[4] = fmaf(acc[4], is, b1.x); acc[5] = fmaf(acc[5], is, b1.y);
    acc[6] = fmaf(acc[6], is, b1.z); acc[7] = fmaf(acc[7], is, b1.w);

    float* out = part ? outP : outA;

    if (mode == 0) {
#pragma unroll
        for (int k = 0; k < 8; k++) acc[k] = fmaxf(acc[k], 0.f);
        *reinterpret_cast<float4*>(&out[node * DIM + q * 8]) =
            make_float4(acc[0], acc[1], acc[2], acc[3]);
        *reinterpret_cast<float4*>(&out[node * DIM + q * 8 + 4]) =
            make_float4(acc[4], acc[5], acc[6], acc[7]);
    } else {
#pragma unroll
        for (int o = 4; o <= 8; o <<= 1)
#pragma unroll
            for (int k = 0; k < 8; k++)
                acc[k] += __shfl_xor_sync(0xffffffffu, acc[k], o);
        if (h == 0) {
            *reinterpret_cast<float4*>(&out[node * F + r * 8]) =
                make_float4(0.25f * acc[0], 0.25f * acc[1], 0.25f * acc[2], 0.25f * acc[3]);
            *reinterpret_cast<float4*>(&out[node * F + r * 8 + 4]) =
                make_float4(0.25f * acc[4], 0.25f * acc[5], 0.25f * acc[6], 0.25f * acc[7]);
        }
    }
}

// ---------------- host orchestration ----------------
extern "C" void kernel_launch(void* const* d_in, const int* in_sizes, int n_in,
                              void* d_out, int out_size)
{
    const float* x_am     = (const float*)d_in[0];
    const float* x_ph     = (const float*)d_in[1];
    const float* exist    = (const float*)d_in[2];
    const float* am_exist = (const float*)d_in[3];

    const int *src, *dst;
    int wbase;
    if (in_sizes[4] == N_EDGES) { src = (const int*)d_in[4];  dst = (const int*)d_in[5];  wbase = 6; }
    else                        { src = (const int*)d_in[20]; dst = (const int*)d_in[21]; wbase = 4; }

    const float *Wg[4], *alg[4], *arg[4], *bg[4];
    for (int g = 0; g < 4; g++) {
        Wg[g]  = (const float*)d_in[wbase + g * 4 + 0];
        alg[g] = (const float*)d_in[wbase + g * 4 + 1];
        arg[g] = (const float*)d_in[wbase + g * 4 + 2];
        bg[g]  = (const float*)d_in[wbase + g * 4 + 3];
    }

    float* out = (float*)d_out;

    const int EB = (N_EDGES + 255) / 256;
    const int GB = (N_NODES + 127) / 128;
    const int NB = (N_NODES * 32 + 255) / 256;

    __half* ft;
    float *hA, *hP;
    cudaGetSymbolAddress((void**)&ft, g_ft16);
    cudaGetSymbolAddress((void**)&hA, g_h_a);
    cudaGetSymbolAddress((void**)&hP, g_h_p);

    static cudaStream_t side = nullptr;
    static cudaEvent_t evFork = nullptr, evCsr = nullptr;
    if (!side) {
        cudaStreamCreateWithFlags(&side, cudaStreamNonBlocking);
        cudaEventCreateWithFlags(&evFork, cudaEventDisableTiming);
        cudaEventCreateWithFlags(&evCsr,  cudaEventDisableTiming);
    }

    dim3 gg(GB, 2);

    // CSR on side stream (launches 1..3), overlaps gemm0
    cudaEventRecord(evFork, 0);
    cudaStreamWaitEvent(side, evFork, 0);
    hist_kernel<<<EB, 256, 0, side>>>(dst);                          // launch 1
    scan_kernel<<<1, 1024, 0, side>>>();                             // launch 2
    scatter_kernel<<<EB, 256, 0, side>>>(src, dst, am_exist, exist); // launch 3
    cudaEventRecord(evCsr, side);

    // gemm0 = 4th submitted kernel (profiled slot)
    gemm_kernel<<<gg, 256>>>(x_am, x_ph, Wg[0], Wg[1], alg[0], alg[1], arg[0], arg[1], ft);

    cudaStreamWaitEvent(0, evCsr, 0);
    agg_kernel<<<NB, 256>>>(ft, bg[0], bg[1], hA, hP, 0);

    gemm_kernel<<<gg, 256>>>(hA, hP, Wg[2], Wg[3], alg[2], alg[3], arg[2], arg[3], ft);
    agg_kernel<<<NB, 256>>>(ft, bg[2], bg[3], out, out + (size_t)N_NODES * F, 1);
}

// round 12
// speedup vs baseline: 1.7602x; 1.7602x over previous
#include <cuda_runtime.h>
#include <cuda_fp16.h>
#include <math.h>

#define N_NODES 50000
#define N_EDGES 800000
#define HEADS   4
#define F       32
#define DIM     128
#define DIM2    256   // interleaved ft row: [A 128 | P 128]

typedef unsigned long long ull;

// ---------------- device scratch ----------------
__device__ __half g_ft16[N_NODES * DIM2];    // interleaved fp16 ft, both streams
__device__ float  g_h_a [N_NODES * DIM];     // layer-0 output (fp32, GEMM input)
__device__ float  g_h_p [N_NODES * DIM];
__device__ float  g_el2 [N_NODES * 8];       // [node][A 4 heads | P 4 heads]
__device__ float  g_er2 [N_NODES * 8];
__device__ int    g_rowptr[N_NODES + 1];
__device__ int    g_cnt [N_NODES];           // zero-init; every call leaves it zeroed
__device__ int    g_src_csr[N_EDGES];
__device__ float2 g_ew_csr[N_EDGES];         // {am_exist, exist}
__device__ __half g_wt16[4 * 128 * 128];     // W^T fp16: [g][n][k]

// ---------------- CSR build ----------------
__global__ void hist_kernel(const int* __restrict__ dst) {
    int i = blockIdx.x * blockDim.x + threadIdx.x;
    if (i < N_EDGES) atomicAdd(&g_cnt[dst[i]], 1);
}

__global__ void scan_kernel() {
    __shared__ int tmp[1024];
    int tid = threadIdx.x;
    const int chunk = (N_NODES + 1023) / 1024;
    int begin = tid * chunk;
    int end   = begin + chunk; if (end > N_NODES) end = N_NODES;
    int sum = 0;
    for (int i = begin; i < end && begin < N_NODES; i++) sum += g_cnt[i];
    tmp[tid] = sum;
    __syncthreads();
    for (int off = 1; off < 1024; off <<= 1) {
        int v = (tid >= off) ? tmp[tid - off] : 0;
        __syncthreads();
        tmp[tid] += v;
        __syncthreads();
    }
    int run = tmp[tid] - sum;
    for (int i = begin; i < end && begin < N_NODES; i++) {
        g_rowptr[i] = run;
        run += g_cnt[i];
    }
    if (tid == 1023) g_rowptr[N_NODES] = tmp[1023];
}

__global__ void scatter_kernel(const int* __restrict__ src, const int* __restrict__ dst,
                               const float* __restrict__ ewa, const float* __restrict__ ewp) {
    int i = blockIdx.x * blockDim.x + threadIdx.x;
    if (i < N_EDGES) {
        int d = dst[i];
        int old = atomicAdd(&g_cnt[d], -1);          // old in [1..deg]; leaves cnt zeroed
        int pos = g_rowptr[d] + old - 1;
        g_src_csr[pos] = src[i];
        g_ew_csr[pos]  = make_float2(ewa[i], ewp[i]);
    }
}

// ---------------- weight prep: W fp32 [k][n] -> W^T fp16 [n][k] ----------------
__global__ void prep_wt_kernel(const float* __restrict__ W0, const float* __restrict__ W1,
                               const float* __restrict__ W2, const float* __restrict__ W3) {
    int i = blockIdx.x * blockDim.x + threadIdx.x;     // 65536 total
    int g = i >> 14;
    int k = (i >> 7) & 127;
    int n = i & 127;
    const float* W = (g == 0) ? W0 : (g == 1) ? W1 : (g == 2) ? W2 : W3;
    g_wt16[(g << 14) + n * 128 + k] = __float2half(W[k * 128 + n]);
}

// ---------------- tensor-core GEMM + fused el/er; fp16 interleaved ft out ----------------
// Block: 64 rows x 128 cols, 256 thr (8 warps): warp = (mw = wid&3) 16 rows x (nh = wid>>2) 64 cols.
// mma.sync.m16n8k16 row.col, fp16 in, fp32 accum. K = 128 (8 k-steps).
#define AS_STRIDE 132
#define WS_STRIDE 132
#define GEMM_SMEM ((64 * AS_STRIDE + 128 * WS_STRIDE) * 2 + 1024)

__device__ __forceinline__ void mma16816(float* d, unsigned a0, unsigned a1, unsigned a2,
                                         unsigned a3, unsigned b0, unsigned b1) {
    asm volatile(
        "mma.sync.aligned.m16n8k16.row.col.f32.f16.f16.f32 "
        "{%0,%1,%2,%3}, {%4,%5,%6,%7}, {%8,%9}, {%0,%1,%2,%3};"
        : "+f"(d[0]), "+f"(d[1]), "+f"(d[2]), "+f"(d[3])
        : "r"(a0), "r"(a1), "r"(a2), "r"(a3), "r"(b0), "r"(b1));
}

__global__ __launch_bounds__(256) void gemm_tc_kernel(
    const float* __restrict__ A0, const float* __restrict__ A1,
    const __half* __restrict__ Wt,   // [2][128][128] (n-major), st-indexed
    const float* __restrict__ al0, const float* __restrict__ al1,
    const float* __restrict__ ar0, const float* __restrict__ ar1,
    __half* __restrict__ C)
{
    extern __shared__ char smem[];
    __half* As = (__half*)smem;                        // [64][AS_STRIDE]
    __half* Ws = As + 64 * AS_STRIDE;                  // [128][WS_STRIDE]
    float*  als = (float*)(Ws + 128 * WS_STRIDE);      // [128]
    float*  ars = als + 128;

    int st = blockIdx.y;
    const float*  A  = st ? A1 : A0;
    const __half* W  = Wt + st * (128 * 128);
    const float*  al = st ? al1 : al0;
    const float*  ar = st ? ar1 : ar0;

    int tid  = threadIdx.x;
    int lane = tid & 31;
    int wid  = tid >> 5;
    int m0   = blockIdx.x * 64;
    int mw   = wid & 3;
    int nh   = wid >> 2;

    // stage A: 64 rows x 128 k, fp32 -> fp16
    for (int i = tid; i < 2048; i += 256) {
        int row = i >> 5, kc = (i & 31) * 4;
        int m = m0 + row;
        float4 x = (m < N_NODES) ? *(const float4*)&A[(size_t)m * 128 + kc]
                                 : make_float4(0.f, 0.f, 0.f, 0.f);
        __half2 h0 = __floats2half2_rn(x.x, x.y);
        __half2 h1 = __floats2half2_rn(x.z, x.w);
        uint2 u;
        u.x = *reinterpret_cast<unsigned*>(&h0);
        u.y = *reinterpret_cast<unsigned*>(&h1);
        *reinterpret_cast<uint2*>(&As[row * AS_STRIDE + kc]) = u;
    }
    // stage W^T: 128 n x 128 k, fp16 copy
    for (int i = tid; i < 4096; i += 256) {
        int n = i >> 5, kc = (i & 31) * 4;
        uint2 u = *reinterpret_cast<const uint2*>(&W[n * 128 + kc]);
        *reinterpret_cast<uint2*>(&Ws[n * WS_STRIDE + kc]) = u;
    }
    if (tid < 128) { als[tid] = al[tid]; ars[tid] = ar[tid]; }
    __syncthreads();

    float acc[8][4];
#pragma unroll
    for (int t = 0; t < 8; t++)
#pragma unroll
        for (int j = 0; j < 4; j++) acc[t][j] = 0.f;

    int r0 = mw * 16 + (lane >> 2);        // A row (fragment)
    int k0 = (lane & 3) * 2;               // k within k-step
    int nb = nh * 64 + (lane >> 2);        // B n base

#pragma unroll
    for (int ks = 0; ks < 8; ks++) {
        int kb = ks * 16 + k0;
        unsigned a0 = *reinterpret_cast<const unsigned*>(&As[r0 * AS_STRIDE + kb]);
        unsigned a1 = *reinterpret_cast<const unsigned*>(&As[(r0 + 8) * AS_STRIDE + kb]);
        unsigned a2 = *reinterpret_cast<const unsigned*>(&As[r0 * AS_STRIDE + kb + 8]);
        unsigned a3 = *reinterpret_cast<const unsigned*>(&As[(r0 + 8) * AS_STRIDE + kb + 8]);
#pragma unroll
        for (int t = 0; t < 8; t++) {
            unsigned b0 = *reinterpret_cast<const unsigned*>(&Ws[(nb + t * 8) * WS_STRIDE + kb]);
            unsigned b1 = *reinterpret_cast<const unsigned*>(&Ws[(nb + t * 8) * WS_STRIDE + kb + 8]);
            mma16816(acc[t], a0, a1, a2, a3, b0, b1);
        }
    }

    // epilogue: fp16 interleaved C store + fused el/er from fp32 accumulators
    int m1 = m0 + r0;
    int m2 = m1 + 8;
    int cb = nh * 64 + (lane & 3) * 2;

    float l1[2] = {0.f, 0.f}, l2[2] = {0.f, 0.f};
    float r1[2] = {0.f, 0.f}, r2[2] = {0.f, 0.f};

#pragma unroll
    for (int t = 0; t < 8; t++) {
        int c  = cb + t * 8;
        int hh = t >> 2;
        float a0c = als[c], a1c = als[c + 1];
        float b0c = ars[c], b1c = ars[c + 1];
        l1[hh] += acc[t][0] * a0c + acc[t][1] * a1c;
        l2[hh] += acc[t][2] * a0c + acc[t][3] * a1c;
        r1[hh] += acc[t][0] * b0c + acc[t][1] * b1c;
        r2[hh] += acc[t][2] * b0c + acc[t][3] * b1c;
        if (m1 < N_NODES) {
            __half2 h = __floats2half2_rn(acc[t][0], acc[t][1]);
            *reinterpret_cast<unsigned*>(&C[(size_t)m1 * DIM2 + st * DIM + c]) =
                *reinterpret_cast<unsigned*>(&h);
        }
        if (m2 < N_NODES) {
            __half2 h = __floats2half2_rn(acc[t][2], acc[t][3]);
            *reinterpret_cast<unsigned*>(&C[(size_t)m2 * DIM2 + st * DIM + c]) =
                *reinterpret_cast<unsigned*>(&h);
        }
    }

    // reduce el/er over the 4 lanes of each row group (lane&3)
#pragma unroll
    for (int off = 1; off <= 2; off <<= 1) {
#pragma unroll
        for (int hh = 0; hh < 2; hh++) {
            l1[hh] += __shfl_xor_sync(0xffffffffu, l1[hh], off);
            l2[hh] += __shfl_xor_sync(0xffffffffu, l2[hh], off);
            r1[hh] += __shfl_xor_sync(0xffffffffu, r1[hh], off);
            r2[hh] += __shfl_xor_sync(0xffffffffu, r2[hh], off);
        }
    }
    if ((lane & 3) == 0) {
#pragma unroll
        for (int hh = 0; hh < 2; hh++) {
            int head = nh * 2 + hh;
            if (m1 < N_NODES) {
                g_el2[m1 * 8 + st * 4 + head] = l1[hh];
                g_er2[m1 * 8 + st * 4 + head] = r1[hh];
            }
            if (m2 < N_NODES) {
                g_el2[m2 * 8 + st * 4 + head] = l2[hh];
                g_er2[m2 * 8 + st * 4 + head] = r2[hh];
            }
        }
    }
}

__device__ __forceinline__ float lrelu(float x) { return x > 0.f ? x : 0.2f * x; }

__device__ __forceinline__ void acc8(float* acc, uint4 u, float p) {
    float2 f0 = __half22float2(*reinterpret_cast<__half2*>(&u.x));
    float2 f1 = __half22float2(*reinterpret_cast<__half2*>(&u.y));
    float2 f2 = __half22float2(*reinterpret_cast<__half2*>(&u.z));
    float2 f3 = __half22float2(*reinterpret_cast<__half2*>(&u.w));
    acc[0] = fmaf(p, f0.x, acc[0]); acc[1] = fmaf(p, f0.y, acc[1]);
    acc[2] = fmaf(p, f1.x, acc[2]); acc[3] = fmaf(p, f1.y, acc[3]);
    acc[4] = fmaf(p, f2.x, acc[4]); acc[5] = fmaf(p, f2.y, acc[5]);
    acc[6] = fmaf(p, f3.x, acc[6]); acc[7] = fmaf(p, f3.y, acc[7]);
}

// ---------------- fused score + aggregation (unchanged from 376 µs best) ----------------
__global__ __launch_bounds__(256) void agg_kernel(
    const __half* __restrict__ ft,
    const float* __restrict__ biasA, const float* __restrict__ biasP,
    float* __restrict__ outA, float* __restrict__ outP, int mode)
{
    __shared__ float sh_p[8][256];
    int wib  = threadIdx.x >> 5;
    int w    = (blockIdx.x * blockDim.x + threadIdx.x) >> 5;
    int lane = threadIdx.x & 31;
    if (w >= N_NODES) return;
    int node = w;
    int beg = g_rowptr[node], end = g_rowptr[node + 1];
    int part = lane >> 4;
    int q    = lane & 15;
    int h    = q >> 2;
    int r    = q & 3;
    int ph   = part * 4 + h;
    int off  = part * DIM + q * 8;
    float* pw = sh_p[wib];

    float4 erA = *reinterpret_cast<const float4*>(&g_er2[node * 8]);
    float4 erP = *reinterpret_cast<const float4*>(&g_er2[node * 8 + 4]);

    float s[8];
#pragma unroll
    for (int k = 0; k < 8; k++) s[k] = 0.f;
    float acc[8];
#pragma unroll
    for (int k = 0; k < 8; k++) acc[k] = 0.f;

    for (int i0 = beg; i0 < end; i0 += 32) {
        int n = end - i0; if (n > 32) n = 32;
        int sn_l = 0;
        float4 pa = make_float4(0.f, 0.f, 0.f, 0.f);
        float4 pp = make_float4(0.f, 0.f, 0.f, 0.f);
        if (lane < n) {
            int i = i0 + lane;
            sn_l = g_src_csr[i];
            float2 ew  = g_ew_csr[i];
            float4 elA = *reinterpret_cast<const float4*>(&g_el2[sn_l * 8]);
            float4 elP = *reinterpret_cast<const float4*>(&g_el2[sn_l * 8 + 4]);
            float e0 = __expf(fminf(lrelu(elA.x + erA.x), 60.f));
            float e1 = __expf(fminf(lrelu(elA.y + erA.y), 60.f));
            float e2 = __expf(fminf(lrelu(elA.z + erA.z), 60.f));
            float e3 = __expf(fminf(lrelu(elA.w + erA.w), 60.f));
            float e4 = __expf(fminf(lrelu(elP.x + erP.x), 60.f));
            float e5 = __expf(fminf(lrelu(elP.y + erP.y), 60.f));
            float e6 = __expf(fminf(lrelu(elP.z + erP.z), 60.f));
            float e7 = __expf(fminf(lrelu(elP.w + erP.w), 60.f));
            s[0] += e0; s[1] += e1; s[2] += e2; s[3] += e3;
            s[4] += e4; s[5] += e5; s[6] += e6; s[7] += e7;
            pa = make_float4(e0 * ew.x, e1 * ew.x, e2 * ew.x, e3 * ew.x);
            pp = make_float4(e4 * ew.y, e5 * ew.y, e6 * ew.y, e7 * ew.y);
        }
        __syncwarp();
        *reinterpret_cast<float4*>(&pw[lane * 8])     = pa;
        *reinterpret_cast<float4*>(&pw[lane * 8 + 4]) = pp;
        __syncwarp();

        int j = 0;
        for (; j + 4 <= n; j += 4) {
            int t0 = __shfl_sync(0xffffffffu, sn_l, j);
            int t1 = __shfl_sync(0xffffffffu, sn_l, j + 1);
            int t2 = __shfl_sync(0xffffffffu, sn_l, j + 2);
            int t3 = __shfl_sync(0xffffffffu, sn_l, j + 3);
            uint4 u0 = *reinterpret_cast<const uint4*>(&ft[(size_t)t0 * DIM2 + off]);
            uint4 u1 = *reinterpret_cast<const uint4*>(&ft[(size_t)t1 * DIM2 + off]);
            uint4 u2 = *reinterpret_cast<const uint4*>(&ft[(size_t)t2 * DIM2 + off]);
            uint4 u3 = *reinterpret_cast<const uint4*>(&ft[(size_t)t3 * DIM2 + off]);
            acc8(acc, u0, pw[(j    ) * 8 + ph]);
            acc8(acc, u1, pw[(j + 1) * 8 + ph]);
            acc8(acc, u2, pw[(j + 2) * 8 + ph]);
            acc8(acc, u3, pw[(j + 3) * 8 + ph]);
        }
        for (; j < n; j++) {
            int t0 = __shfl_sync(0xffffffffu, sn_l, j);
            uint4 u0 = *reinterpret_cast<const uint4*>(&ft[(size_t)t0 * DIM2 + off]);
            acc8(acc, u0, pw[j * 8 + ph]);
        }
    }

#pragma unroll
    for (int o = 16; o; o >>= 1)
#pragma unroll
        for (int k = 0; k < 8; k++)
            s[k] += __shfl_xor_sync(0xffffffffu, s[k], o);

    float is = 1.f / fmaxf(s[ph], 1e-9f);

    const float* bias = part ? biasP : biasA;
    float4 b0 = *reinterpret_cast<const float4*>(&bias[h * F + r * 8]);
    float4 b1 = *reinterpret_cast<const float4*>(&bias[h * F + r * 8 + 4]);
    acc[0] = fmaf(acc[0], is, b0.x); acc[1] = fmaf(acc[1], is, b0.y);
    acc[2] = fmaf(acc[2], is, b0.z); acc[3] = fmaf(acc[3], is, b0.w);
    acc[4] = fmaf(acc[4], is, b1.x); acc[5] = fmaf(acc[5], is, b1.y);
    acc[6] = fmaf(acc[6], is, b1.z); acc[7] = fmaf(acc[7], is, b1.w);

    float* out = part ? outP : outA;

    if (mode == 0) {
#pragma unroll
        for (int k = 0; k < 8; k++) acc[k] = fmaxf(acc[k], 0.f);
        *reinterpret_cast<float4*>(&out[node * DIM + q * 8]) =
            make_float4(acc[0], acc[1], acc[2], acc[3]);
        *reinterpret_cast<float4*>(&out[node * DIM + q * 8 + 4]) =
            make_float4(acc[4], acc[5], acc[6], acc[7]);
    } else {
#pragma unroll
        for (int o = 4; o <= 8; o <<= 1)
#pragma unroll
            for (int k = 0; k < 8; k++)
                acc[k] += __shfl_xor_sync(0xffffffffu, acc[k], o);
        if (h == 0) {
            *reinterpret_cast<float4*>(&out[node * F + r * 8]) =
                make_float4(0.25f * acc[0], 0.25f * acc[1], 0.25f * acc[2], 0.25f * acc[3]);
            *reinterpret_cast<float4*>(&out[node * F + r * 8 + 4]) =
                make_float4(0.25f * acc[4], 0.25f * acc[5], 0.25f * acc[6], 0.25f * acc[7]);
        }
    }
}

// ---------------- host orchestration ----------------
extern "C" void kernel_launch(void* const* d_in, const int* in_sizes, int n_in,
                              void* d_out, int out_size)
{
    const float* x_am     = (const float*)d_in[0];
    const float* x_ph     = (const float*)d_in[1];
    const float* exist    = (const float*)d_in[2];
    const float* am_exist = (const float*)d_in[3];

    const int *src, *dst;
    int wbase;
    if (in_sizes[4] == N_EDGES) { src = (const int*)d_in[4];  dst = (const int*)d_in[5];  wbase = 6; }
    else                        { src = (const int*)d_in[20]; dst = (const int*)d_in[21]; wbase = 4; }

    const float *Wg[4], *alg[4], *arg[4], *bg[4];
    for (int g = 0; g < 4; g++) {
        Wg[g]  = (const float*)d_in[wbase + g * 4 + 0];
        alg[g] = (const float*)d_in[wbase + g * 4 + 1];
        arg[g] = (const float*)d_in[wbase + g * 4 + 2];
        bg[g]  = (const float*)d_in[wbase + g * 4 + 3];
    }

    float* out = (float*)d_out;

    const int EB  = (N_EDGES + 255) / 256;
    const int GB2 = (N_NODES + 63) / 64;
    const int NB  = (N_NODES * 32 + 255) / 256;

    __half *ft, *wt;
    float *hA, *hP;
    cudaGetSymbolAddress((void**)&ft, g_ft16);
    cudaGetSymbolAddress((void**)&wt, g_wt16);
    cudaGetSymbolAddress((void**)&hA, g_h_a);
    cudaGetSymbolAddress((void**)&hP, g_h_p);

    static cudaStream_t side = nullptr;
    static cudaEvent_t evFork = nullptr, evPrep = nullptr, evCsr = nullptr;
    if (!side) {
        cudaStreamCreateWithFlags(&side, cudaStreamNonBlocking);
        cudaEventCreateWithFlags(&evFork, cudaEventDisableTiming);
        cudaEventCreateWithFlags(&evPrep, cudaEventDisableTiming);
        cudaEventCreateWithFlags(&evCsr,  cudaEventDisableTiming);
        cudaFuncSetAttribute(gemm_tc_kernel,
                             cudaFuncAttributeMaxDynamicSharedMemorySize, GEMM_SMEM);
    }

    dim3 gg(GB2, 2);

    // side stream: weight prep then CSR build (all overlap gemm0)
    cudaEventRecord(evFork, 0);
    cudaStreamWaitEvent(side, evFork, 0);
    prep_wt_kernel<<<256, 256, 0, side>>>(Wg[0], Wg[1], Wg[2], Wg[3]);
    cudaEventRecord(evPrep, side);
    hist_kernel<<<EB, 256, 0, side>>>(dst);
    scan_kernel<<<1, 1024, 0, side>>>();
    scatter_kernel<<<EB, 256, 0, side>>>(src, dst, am_exist, exist);
    cudaEventRecord(evCsr, side);

    // layer 0
    cudaStreamWaitEvent(0, evPrep, 0);
    gemm_tc_kernel<<<gg, 256, GEMM_SMEM>>>(x_am, x_ph, wt,
                                           alg[0], alg[1], arg[0], arg[1], ft);
    cudaStreamWaitEvent(0, evCsr, 0);
    agg_kernel<<<NB, 256>>>(ft, bg[0], bg[1], hA, hP, 0);

    // layer 1 (+ fused head-mean)
    gemm_tc_kernel<<<gg, 256, GEMM_SMEM>>>(hA, hP, wt + 2 * 128 * 128,
                                           alg[2], alg[3], arg[2], arg[3], ft);
    agg_kernel<<<NB, 256>>>(ft, bg[2], bg[3], out, out + (size_t)N_NODES * F, 1);
}

// round 13
// speedup vs baseline: 1.7698x; 1.0054x over previous
#include <cuda_runtime.h>
#include <cuda_fp16.h>
#include <math.h>

#define N_NODES 50000
#define N_EDGES 800000
#define HEADS   4
#define F       32
#define DIM     128
#define DIM2    256   // interleaved ft row: [A 128 | P 128]

typedef unsigned long long ull;

// ---------------- device scratch ----------------
__device__ __half g_ft16[N_NODES * DIM2];    // interleaved fp16 ft, both streams
__device__ float  g_h_a [N_NODES * DIM];     // layer-0 output (fp32, GEMM input)
__device__ float  g_h_p [N_NODES * DIM];
__device__ float  g_el2 [N_NODES * 8];       // [node][A 4 heads | P 4 heads]
__device__ float  g_er2 [N_NODES * 8];
__device__ int    g_rowptr[N_NODES + 1];
__device__ int    g_cnt [N_NODES];           // zero-init; every call leaves it zeroed
__device__ int    g_src_csr[N_EDGES];
__device__ float2 g_ew_csr[N_EDGES];         // {am_exist, exist}

// ---------------- CSR build ----------------
__global__ void hist_kernel(const int* __restrict__ dst) {
    int i = blockIdx.x * blockDim.x + threadIdx.x;
    if (i < N_EDGES) atomicAdd(&g_cnt[dst[i]], 1);
}

__global__ void scan_kernel() {
    __shared__ int tmp[1024];
    int tid = threadIdx.x;
    const int chunk = (N_NODES + 1023) / 1024;
    int begin = tid * chunk;
    int end   = begin + chunk; if (end > N_NODES) end = N_NODES;
    int sum = 0;
    for (int i = begin; i < end && begin < N_NODES; i++) sum += g_cnt[i];
    tmp[tid] = sum;
    __syncthreads();
    for (int off = 1; off < 1024; off <<= 1) {
        int v = (tid >= off) ? tmp[tid - off] : 0;
        __syncthreads();
        tmp[tid] += v;
        __syncthreads();
    }
    int run = tmp[tid] - sum;
    for (int i = begin; i < end && begin < N_NODES; i++) {
        g_rowptr[i] = run;
        run += g_cnt[i];
    }
    if (tid == 1023) g_rowptr[N_NODES] = tmp[1023];
}

__global__ void scatter_kernel(const int* __restrict__ src, const int* __restrict__ dst,
                               const float* __restrict__ ewa, const float* __restrict__ ewp) {
    int i = blockIdx.x * blockDim.x + threadIdx.x;
    if (i < N_EDGES) {
        int d = dst[i];
        int old = atomicAdd(&g_cnt[d], -1);          // old in [1..deg]; leaves cnt zeroed
        int pos = g_rowptr[d] + old - 1;
        g_src_csr[pos] = src[i];
        g_ew_csr[pos]  = make_float2(ewa[i], ewp[i]);
    }
}

// ---------------- tensor-core GEMM (fused W transpose) + fused el/er ----------------
// Block: 64 rows x 128 cols, 256 thr (8 warps): warp = (mw) 16 rows x (nh) 64 cols.
// mma.sync.m16n8k16 row.col, fp16 in, fp32 accum. K = 128 (8 k-steps).
// W fp32 [k][n] is transposed+converted into smem per block (no prep kernel).
#define AS_STRIDE 136
#define WS_STRIDE 136
#define GEMM_SMEM ((64 * AS_STRIDE + 128 * WS_STRIDE) * 2 + 1024)

__device__ __forceinline__ void mma16816(float* d, unsigned a0, unsigned a1, unsigned a2,
                                         unsigned a3, unsigned b0, unsigned b1) {
    asm volatile(
        "mma.sync.aligned.m16n8k16.row.col.f32.f16.f16.f32 "
        "{%0,%1,%2,%3}, {%4,%5,%6,%7}, {%8,%9}, {%0,%1,%2,%3};"
        : "+f"(d[0]), "+f"(d[1]), "+f"(d[2]), "+f"(d[3])
        : "r"(a0), "r"(a1), "r"(a2), "r"(a3), "r"(b0), "r"(b1));
}

__global__ __launch_bounds__(256) void gemm_tc_kernel(
    const float* __restrict__ A0, const float* __restrict__ A1,
    const float* __restrict__ W0, const float* __restrict__ W1,   // fp32 [k][n]
    const float* __restrict__ al0, const float* __restrict__ al1,
    const float* __restrict__ ar0, const float* __restrict__ ar1,
    __half* __restrict__ C)
{
    extern __shared__ char smem[];
    __half* As = (__half*)smem;                        // [64][AS_STRIDE]
    __half* Ws = As + 64 * AS_STRIDE;                  // [128][WS_STRIDE] (W^T: [n][k])
    float*  als = (float*)(Ws + 128 * WS_STRIDE);      // [128]
    float*  ars = als + 128;

    int st = blockIdx.y;
    const float* A  = st ? A1 : A0;
    const float* W  = st ? W1 : W0;
    const float* al = st ? al1 : al0;
    const float* ar = st ? ar1 : ar0;

    int tid  = threadIdx.x;
    int lane = tid & 31;
    int wid  = tid >> 5;
    int m0   = blockIdx.x * 64;
    int mw   = wid & 3;
    int nh   = wid >> 2;

    // stage A: 64 rows x 128 k, fp32 -> fp16
    for (int i = tid; i < 2048; i += 256) {
        int row = i >> 5, kc = (i & 31) * 4;
        int m = m0 + row;
        float4 x = (m < N_NODES) ? *(const float4*)&A[(size_t)m * 128 + kc]
                                 : make_float4(0.f, 0.f, 0.f, 0.f);
        __half2 h0 = __floats2half2_rn(x.x, x.y);
        __half2 h1 = __floats2half2_rn(x.z, x.w);
        uint2 u;
        u.x = *reinterpret_cast<unsigned*>(&h0);
        u.y = *reinterpret_cast<unsigned*>(&h1);
        *reinterpret_cast<uint2*>(&As[row * AS_STRIDE + kc]) = u;
    }
    // stage W^T: read W fp32 [k][n] coalesced along n, write fp16 transposed [n][k]
    for (int i = tid; i < 4096; i += 256) {
        int n  = i & 127;
        int k4 = (i >> 7) * 4;         // k block of 4
#pragma unroll
        for (int j = 0; j < 4; j++)
            Ws[n * WS_STRIDE + k4 + j] = __float2half(W[(k4 + j) * 128 + n]);
    }
    if (tid < 128) { als[tid] = al[tid]; ars[tid] = ar[tid]; }
    __syncthreads();

    float acc[8][4];
#pragma unroll
    for (int t = 0; t < 8; t++)
#pragma unroll
        for (int j = 0; j < 4; j++) acc[t][j] = 0.f;

    int r0 = mw * 16 + (lane >> 2);        // A row (fragment)
    int k0 = (lane & 3) * 2;               // k within k-step
    int nb = nh * 64 + (lane >> 2);        // B n base

#pragma unroll
    for (int ks = 0; ks < 8; ks++) {
        int kb = ks * 16 + k0;
        unsigned a0 = *reinterpret_cast<const unsigned*>(&As[r0 * AS_STRIDE + kb]);
        unsigned a1 = *reinterpret_cast<const unsigned*>(&As[(r0 + 8) * AS_STRIDE + kb]);
        unsigned a2 = *reinterpret_cast<const unsigned*>(&As[r0 * AS_STRIDE + kb + 8]);
        unsigned a3 = *reinterpret_cast<const unsigned*>(&As[(r0 + 8) * AS_STRIDE + kb + 8]);
#pragma unroll
        for (int t = 0; t < 8; t++) {
            unsigned b0 = *reinterpret_cast<const unsigned*>(&Ws[(nb + t * 8) * WS_STRIDE + kb]);
            unsigned b1 = *reinterpret_cast<const unsigned*>(&Ws[(nb + t * 8) * WS_STRIDE + kb + 8]);
            mma16816(acc[t], a0, a1, a2, a3, b0, b1);
        }
    }

    // epilogue: fp16 interleaved C store + fused el/er from fp32 accumulators
    int m1 = m0 + r0;
    int m2 = m1 + 8;
    int cb = nh * 64 + (lane & 3) * 2;

    float l1[2] = {0.f, 0.f}, l2[2] = {0.f, 0.f};
    float r1[2] = {0.f, 0.f}, r2[2] = {0.f, 0.f};

#pragma unroll
    for (int t = 0; t < 8; t++) {
        int c  = cb + t * 8;
        int hh = t >> 2;
        float a0c = als[c], a1c = als[c + 1];
        float b0c = ars[c], b1c = ars[c + 1];
        l1[hh] += acc[t][0] * a0c + acc[t][1] * a1c;
        l2[hh] += acc[t][2] * a0c + acc[t][3] * a1c;
        r1[hh] += acc[t][0] * b0c + acc[t][1] * b1c;
        r2[hh] += acc[t][2] * b0c + acc[t][3] * b1c;
        if (m1 < N_NODES) {
            __half2 h = __floats2half2_rn(acc[t][0], acc[t][1]);
            *reinterpret_cast<unsigned*>(&C[(size_t)m1 * DIM2 + st * DIM + c]) =
                *reinterpret_cast<unsigned*>(&h);
        }
        if (m2 < N_NODES) {
            __half2 h = __floats2half2_rn(acc[t][2], acc[t][3]);
            *reinterpret_cast<unsigned*>(&C[(size_t)m2 * DIM2 + st * DIM + c]) =
                *reinterpret_cast<unsigned*>(&h);
        }
    }

#pragma unroll
    for (int off = 1; off <= 2; off <<= 1) {
#pragma unroll
        for (int hh = 0; hh < 2; hh++) {
            l1[hh] += __shfl_xor_sync(0xffffffffu, l1[hh], off);
            l2[hh] += __shfl_xor_sync(0xffffffffu, l2[hh], off);
            r1[hh] += __shfl_xor_sync(0xffffffffu, r1[hh], off);
            r2[hh] += __shfl_xor_sync(0xffffffffu, r2[hh], off);
        }
    }
    if ((lane & 3) == 0) {
#pragma unroll
        for (int hh = 0; hh < 2; hh++) {
            int head = nh * 2 + hh;
            if (m1 < N_NODES) {
                g_el2[m1 * 8 + st * 4 + head] = l1[hh];
                g_er2[m1 * 8 + st * 4 + head] = r1[hh];
            }
            if (m2 < N_NODES) {
                g_el2[m2 * 8 + st * 4 + head] = l2[hh];
                g_er2[m2 * 8 + st * 4 + head] = r2[hh];
            }
        }
    }
}

__device__ __forceinline__ float lrelu(float x) { return x > 0.f ? x : 0.2f * x; }

__device__ __forceinline__ void acc8(float* acc, uint4 u, float p) {
    float2 f0 = __half22float2(*reinterpret_cast<__half2*>(&u.x));
    float2 f1 = __half22float2(*reinterpret_cast<__half2*>(&u.y));
    float2 f2 = __half22float2(*reinterpret_cast<__half2*>(&u.z));
    float2 f3 = __half22float2(*reinterpret_cast<__half2*>(&u.w));
    acc[0] = fmaf(p, f0.x, acc[0]); acc[1] = fmaf(p, f0.y, acc[1]);
    acc[2] = fmaf(p, f1.x, acc[2]); acc[3] = fmaf(p, f1.y, acc[3]);
    acc[4] = fmaf(p, f2.x, acc[4]); acc[5] = fmaf(p, f2.y, acc[5]);
    acc[6] = fmaf(p, f3.x, acc[6]); acc[7] = fmaf(p, f3.y, acc[7]);
}

// ---------------- fused score + aggregation (unchanged from 343.7 µs best) ----------------
__global__ __launch_bounds__(256) void agg_kernel(
    const __half* __restrict__ ft,
    const float* __restrict__ biasA, const float* __restrict__ biasP,
    float* __restrict__ outA, float* __restrict__ outP, int mode)
{
    __shared__ float sh_p[8][256];
    int wib  = threadIdx.x >> 5;
    int w    = (blockIdx.x * blockDim.x + threadIdx.x) >> 5;
    int lane = threadIdx.x & 31;
    if (w >= N_NODES) return;
    int node = w;
    int beg = g_rowptr[node], end = g_rowptr[node + 1];
    int part = lane >> 4;
    int q    = lane & 15;
    int h    = q >> 2;
    int r    = q & 3;
    int ph   = part * 4 + h;
    int off  = part * DIM + q * 8;
    float* pw = sh_p[wib];

    float4 erA = *reinterpret_cast<const float4*>(&g_er2[node * 8]);
    float4 erP = *reinterpret_cast<const float4*>(&g_er2[node * 8 + 4]);

    float s[8];
#pragma unroll
    for (int k = 0; k < 8; k++) s[k] = 0.f;
    float acc[8];
#pragma unroll
    for (int k = 0; k < 8; k++) acc[k] = 0.f;

    for (int i0 = beg; i0 < end; i0 += 32) {
        int n = end - i0; if (n > 32) n = 32;
        int sn_l = 0;
        float4 pa = make_float4(0.f, 0.f, 0.f, 0.f);
        float4 pp = make_float4(0.f, 0.f, 0.f, 0.f);
        if (lane < n) {
            int i = i0 + lane;
            sn_l = g_src_csr[i];
            float2 ew  = g_ew_csr[i];
            float4 elA = *reinterpret_cast<const float4*>(&g_el2[sn_l * 8]);
            float4 elP = *reinterpret_cast<const float4*>(&g_el2[sn_l * 8 + 4]);
            float e0 = __expf(fminf(lrelu(elA.x + erA.x), 60.f));
            float e1 = __expf(fminf(lrelu(elA.y + erA.y), 60.f));
            float e2 = __expf(fminf(lrelu(elA.z + erA.z), 60.f));
            float e3 = __expf(fminf(lrelu(elA.w + erA.w), 60.f));
            float e4 = __expf(fminf(lrelu(elP.x + erP.x), 60.f));
            float e5 = __expf(fminf(lrelu(elP.y + erP.y), 60.f));
            float e6 = __expf(fminf(lrelu(elP.z + erP.z), 60.f));
            float e7 = __expf(fminf(lrelu(elP.w + erP.w), 60.f));
            s[0] += e0; s[1] += e1; s[2] += e2; s[3] += e3;
            s[4] += e4; s[5] += e5; s[6] += e6; s[7] += e7;
            pa = make_float4(e0 * ew.x, e1 * ew.x, e2 * ew.x, e3 * ew.x);
            pp = make_float4(e4 * ew.y, e5 * ew.y, e6 * ew.y, e7 * ew.y);
        }
        __syncwarp();
        *reinterpret_cast<float4*>(&pw[lane * 8])     = pa;
        *reinterpret_cast<float4*>(&pw[lane * 8 + 4]) = pp;
        __syncwarp();

        int j = 0;
        for (; j + 4 <= n; j += 4) {
            int t0 = __shfl_sync(0xffffffffu, sn_l, j);
            int t1 = __shfl_sync(0xffffffffu, sn_l, j + 1);
            int t2 = __shfl_sync(0xffffffffu, sn_l, j + 2);
            int t3 = __shfl_sync(0xffffffffu, sn_l, j + 3);
            uint4 u0 = *reinterpret_cast<const uint4*>(&ft[(size_t)t0 * DIM2 + off]);
            uint4 u1 = *reinterpret_cast<const uint4*>(&ft[(size_t)t1 * DIM2 + off]);
            uint4 u2 = *reinterpret_cast<const uint4*>(&ft[(size_t)t2 * DIM2 + off]);
            uint4 u3 = *reinterpret_cast<const uint4*>(&ft[(size_t)t3 * DIM2 + off]);
            acc8(acc, u0, pw[(j    ) * 8 + ph]);
            acc8(acc, u1, pw[(j + 1) * 8 + ph]);
            acc8(acc, u2, pw[(j + 2) * 8 + ph]);
            acc8(acc, u3, pw[(j + 3) * 8 + ph]);
        }
        for (; j < n; j++) {
            int t0 = __shfl_sync(0xffffffffu, sn_l, j);
            uint4 u0 = *reinterpret_cast<const uint4*>(&ft[(size_t)t0 * DIM2 + off]);
            acc8(acc, u0, pw[j * 8 + ph]);
        }
    }

#pragma unroll
    for (int o = 16; o; o >>= 1)
#pragma unroll
        for (int k = 0; k < 8; k++)
            s[k] += __shfl_xor_sync(0xffffffffu, s[k], o);

    float is = 1.f / fmaxf(s[ph], 1e-9f);

    const float* bias = part ? biasP : biasA;
    float4 b0 = *reinterpret_cast<const float4*>(&bias[h * F + r * 8]);
    float4 b1 = *reinterpret_cast<const float4*>(&bias[h * F + r * 8 + 4]);
    acc[0] = fmaf(acc[0], is, b0.x); acc[1] = fmaf(acc[1], is, b0.y);
    acc[2] = fmaf(acc[2], is, b0.z); acc[3] = fmaf(acc[3], is, b0.w);
    acc[4] = fmaf(acc[4], is, b1.x); acc[5] = fmaf(acc[5], is, b1.y);
    acc[6] = fmaf(acc[6], is, b1.z); acc[7] = fmaf(acc[7], is, b1.w);

    float* out = part ? outP : outA;

    if (mode == 0) {
#pragma unroll
        for (int k = 0; k < 8; k++) acc[k] = fmaxf(acc[k], 0.f);
        *reinterpret_cast<float4*>(&out[node * DIM + q * 8]) =
            make_float4(acc[0], acc[1], acc[2], acc[3]);
        *reinterpret_cast<float4*>(&out[node * DIM + q * 8 + 4]) =
            make_float4(acc[4], acc[5], acc[6], acc[7]);
    } else {
#pragma unroll
        for (int o = 4; o <= 8; o <<= 1)
#pragma unroll
            for (int k = 0; k < 8; k++)
                acc[k] += __shfl_xor_sync(0xffffffffu, acc[k], o);
        if (h == 0) {
            *reinterpret_cast<float4*>(&out[node * F + r * 8]) =
                make_float4(0.25f * acc[0], 0.25f * acc[1], 0.25f * acc[2], 0.25f * acc[3]);
            *reinterpret_cast<float4*>(&out[node * F + r * 8 + 4]) =
                make_float4(0.25f * acc[4], 0.25f * acc[5], 0.25f * acc[6], 0.25f * acc[7]);
        }
    }
}

// ---------------- host orchestration ----------------
extern "C" void kernel_launch(void* const* d_in, const int* in_sizes, int n_in,
                              void* d_out, int out_size)
{
    const float* x_am     = (const float*)d_in[0];
    const float* x_ph     = (const float*)d_in[1];
    const float* exist    = (const float*)d_in[2];
    const float* am_exist = (const float*)d_in[3];

    const int *src, *dst;
    int wbase;
    if (in_sizes[4] == N_EDGES) { src = (const int*)d_in[4];  dst = (const int*)d_in[5];  wbase = 6; }
    else                        { src = (const int*)d_in[20]; dst = (const int*)d_in[21]; wbase = 4; }

    const float *Wg[4], *alg[4], *arg[4], *bg[4];
    for (int g = 0; g < 4; g++) {
        Wg[g]  = (const float*)d_in[wbase + g * 4 + 0];
        alg[g] = (const float*)d_in[wbase + g * 4 + 1];
        arg[g] = (const float*)d_in[wbase + g * 4 + 2];
        bg[g]  = (const float*)d_in[wbase + g * 4 + 3];
    }

    float* out = (float*)d_out;

    const int EB  = (N_EDGES + 255) / 256;
    const int GB2 = (N_NODES + 63) / 64;
    const int NB  = (N_NODES * 32 + 255) / 256;

    __half* ft;
    float *hA, *hP;
    cudaGetSymbolAddress((void**)&ft, g_ft16);
    cudaGetSymbolAddress((void**)&hA, g_h_a);
    cudaGetSymbolAddress((void**)&hP, g_h_p);

    static cudaStream_t side = nullptr;
    static cudaEvent_t evFork = nullptr, evCsr = nullptr;
    if (!side) {
        cudaStreamCreateWithFlags(&side, cudaStreamNonBlocking);
        cudaEventCreateWithFlags(&evFork, cudaEventDisableTiming);
        cudaEventCreateWithFlags(&evCsr,  cudaEventDisableTiming);
        cudaFuncSetAttribute(gemm_tc_kernel,
                             cudaFuncAttributeMaxDynamicSharedMemorySize, GEMM_SMEM);
    }

    dim3 gg(GB2, 2);

    // CSR on side stream (launches 1..3), overlaps gemm0
    cudaEventRecord(evFork, 0);
    cudaStreamWaitEvent(side, evFork, 0);
    hist_kernel<<<EB, 256, 0, side>>>(dst);                          // launch 1
    scan_kernel<<<1, 1024, 0, side>>>();                             // launch 2
    scatter_kernel<<<EB, 256, 0, side>>>(src, dst, am_exist, exist); // launch 3
    cudaEventRecord(evCsr, side);

    // layer 0: gemm0 = 4th submitted kernel (profiled slot)
    gemm_tc_kernel<<<gg, 256, GEMM_SMEM>>>(x_am, x_ph, Wg[0], Wg[1],
                                           alg[0], alg[1], arg[0], arg[1], ft);
    cudaStreamWaitEvent(0, evCsr, 0);
    agg_kernel<<<NB, 256>>>(ft, bg[0], bg[1], hA, hP, 0);

    // layer 1 (+ fused head-mean)
    gemm_tc_kernel<<<gg, 256, GEMM_SMEM>>>(hA, hP, Wg[2], Wg[3],
                                           alg[2], alg[3], arg[2], arg[3], ft);
    agg_kernel<<<NB, 256>>>(ft, bg[2], bg[3], out, out + (size_t)N_NODES * F, 1);
}